// round 3
// baseline (speedup 1.0000x reference)
#include <cuda_runtime.h>
#include <math.h>

#define BB 4
#define NPTS 1024
#define ROWS (BB*NPTS)   /* 4096 */
#define DD 128
#define KG 100
#define PART 32          /* partial-sum blocks for BN */

/* ---------------- device scratch (no allocations allowed) ---------------- */
__device__ float  g_bufA[ROWS*DD];     // fm_l
__device__ float  g_bufB[ROWS*DD];     // fm_m chain
__device__ float  g_bufC[ROWS*DD];     // fm_g chain
__device__ float  g_FO[ROWS*2*DD];     // gemm output fo (fc|fs)
__device__ int    g_nbr[ROWS*KG];      // 100 nearest (sorted; prefixes = k=5/20)
__device__ float  g_dirs[6][3*DD];     // normalized dirs: l,m0,m1,g0,g1,g2
__device__ double g_ps [6][PART][DD];  // BN partial sums
__device__ double g_ps2[6][PART][DD];  // BN partial sumsq

__device__ __forceinline__ float* bufsel(int id) {
    return id == 0 ? g_bufA : (id == 1 ? g_bufB : g_bufC);
}

/* ---------------- prep: normalize direction matrices --------------------- */
__global__ void prep_kernel(const float* dl, const float* dm0, const float* dm1,
                            const float* dg0, const float* dg1, const float* dg2) {
    const float* src[6] = {dl, dm0, dm1, dg0, dg1, dg2};
    for (int t = threadIdx.x; t < 6*DD; t += blockDim.x) {
        int w = t / DD, c = t % DD;
        const float* s = src[w];
        float x = s[c], y = s[DD + c], z = s[2*DD + c];
        float inv = 1.0f / fmaxf(sqrtf(x*x + y*y + z*z), 1e-12f);
        g_dirs[w][c]        = x * inv;
        g_dirs[w][DD + c]   = y * inv;
        g_dirs[w][2*DD + c] = z * inv;
    }
}

/* ---------------- KNN: per-point bitonic sort of 1024 keys --------------- */
__global__ void knn_kernel(const float* __restrict__ verts) {
    __shared__ unsigned long long keys[NPTS];
    int p = blockIdx.x;                 // global point id
    int b = p >> 10, i = p & (NPTS - 1);
    const float* vb = verts + (size_t)b * NPTS * 3;
    float xi = vb[i*3], yi = vb[i*3+1], zi = vb[i*3+2];
    float sqi = xi*xi + yi*yi + zi*zi;

    for (int j = threadIdx.x; j < NPTS; j += blockDim.x) {
        float xj = vb[j*3], yj = vb[j*3+1], zj = vb[j*3+2];
        float sqj = xj*xj + yj*yj + zj*zj;
        float dot = xi*xj + yi*yj + zi*zj;
        float d   = sqi + sqj - 2.0f * dot;       // matches reference formula
        unsigned int fb = __float_as_uint(d);
        fb = (fb & 0x80000000u) ? ~fb : (fb | 0x80000000u);   // order-preserving
        keys[j] = ((unsigned long long)fb << 32) | (unsigned int)j;
    }
    __syncthreads();

    for (int kk = 2; kk <= NPTS; kk <<= 1) {
        for (int jj = kk >> 1; jj > 0; jj >>= 1) {
            for (int t = threadIdx.x; t < NPTS; t += blockDim.x) {
                int ixj = t ^ jj;
                if (ixj > t) {
                    unsigned long long a = keys[t], c = keys[ixj];
                    bool up = ((t & kk) == 0);
                    if ((a > c) == up) { keys[t] = c; keys[ixj] = a; }
                }
            }
            __syncthreads();
        }
    }
    if (threadIdx.x < KG)
        g_nbr[p*KG + threadIdx.x] = (int)(keys[1 + threadIdx.x] & 0xFFFFFFFFu);
}

/* ---------------- conv_surface for the three scales ---------------------- */
__global__ void surf_kernel(const float* __restrict__ verts) {
    int p = blockIdx.x, which = blockIdx.y;           // which: 0=l,1=m0,2=g0
    int K     = (which == 0) ? 5 : ((which == 1) ? 20 : 100);
    int ds    = (which == 0) ? 0 : ((which == 1) ? 1 : 3);
    float* out = (which == 0) ? g_bufA : ((which == 1) ? g_bufB : g_bufC);
    int b = p >> 10, i = p & (NPTS - 1);
    const float* vb = verts + (size_t)b * NPTS * 3;
    int d = threadIdx.x;
    float dx = g_dirs[ds][d], dy = g_dirs[ds][DD + d], dz = g_dirs[ds][2*DD + d];
    float xi = vb[i*3], yi = vb[i*3+1], zi = vb[i*3+2];
    const int* nb = g_nbr + p*KG;
    float m = 0.0f;                                   // max of relu >= 0
    for (int k = 0; k < K; ++k) {
        int j = nb[k];
        float ex = vb[j*3]-xi, ey = vb[j*3+1]-yi, ez = vb[j*3+2]-zi;
        float inv = 1.0f / fmaxf(sqrtf(ex*ex + ey*ey + ez*ez), 1e-12f);
        float th  = (ex*dx + ey*dy + ez*dz) * inv;
        m = fmaxf(m, th);
    }
    out[p*DD + d] = m;
}

/* ---------------- BN stats (deterministic 2-stage) ------------------------ */
__global__ void stats_kernel(int bufid, int slot) {
    const float* buf = bufsel(bufid);
    int d = threadIdx.x, blk = blockIdx.x;
    double s = 0.0, s2 = 0.0;
    int r0 = blk * (ROWS / PART);
    for (int r = r0; r < r0 + ROWS / PART; ++r) {
        float x = buf[r*DD + d];
        s += x; s2 += (double)x * x;
    }
    g_ps [slot][blk][d] = s;
    g_ps2[slot][blk][d] = s2;
}

__global__ void bnapply_kernel(int bufid, int slot,
                               const float* __restrict__ g, const float* __restrict__ be) {
    float* buf = bufsel(bufid);
    int d = threadIdx.x, blk = blockIdx.x;
    double s = 0.0, s2 = 0.0;
    for (int pb = 0; pb < PART; ++pb) { s += g_ps[slot][pb][d]; s2 += g_ps2[slot][pb][d]; }
    double mean = s / ROWS;
    float var = (float)(s2 / ROWS - mean * mean);
    float mf = (float)mean;
    float sc = rsqrtf(var + 1e-5f) * g[d];
    float bb = be[d];
    int r0 = blk * (ROWS / PART);
    for (int r = r0; r < r0 + ROWS / PART; ++r) {
        float x = buf[r*DD + d];
        buf[r*DD + d] = fmaxf((x - mf) * sc + bb, 0.0f);
    }
}

/* ---------------- GEMM: fo = X(4096x128) @ W(128x256) + b ---------------- */
__global__ void gemm_kernel(int xid, const float* __restrict__ W,
                            const float* __restrict__ bias) {
    __shared__ float sx[16*DD];
    const float* X = bufsel(xid);
    int r0 = blockIdx.x * 16;
    for (int idx = threadIdx.x; idx < 16*DD; idx += blockDim.x)
        sx[idx] = X[r0*DD + idx];
    __syncthreads();
    int col = threadIdx.x;                 // 0..255
    float acc[16];
    float bv = bias[col];
    #pragma unroll
    for (int r = 0; r < 16; ++r) acc[r] = bv;
    for (int k = 0; k < DD; ++k) {
        float w = W[k*256 + col];
        #pragma unroll
        for (int r = 0; r < 16; ++r) acc[r] += sx[r*DD + k] * w;
    }
    #pragma unroll
    for (int r = 0; r < 16; ++r)
        g_FO[(size_t)(r0 + r)*2*DD + col] = acc[r];
}

/* ---------------- conv_layer combine: fc + max_k(theta*fs[nbr]) ----------- */
__global__ void convlayer_kernel(const float* __restrict__ verts,
                                 int dirslot, int K, int outid) {
    int p = blockIdx.x;
    int b = p >> 10, i = p & (NPTS - 1);
    const float* vb = verts + (size_t)b * NPTS * 3;
    int d = threadIdx.x;
    float dx = g_dirs[dirslot][d], dy = g_dirs[dirslot][DD + d], dz = g_dirs[dirslot][2*DD + d];
    float xi = vb[i*3], yi = vb[i*3+1], zi = vb[i*3+2];
    const int* nb = g_nbr + p*KG;
    int base = b * NPTS;
    float m = -3.4e38f;
    for (int k = 0; k < K; ++k) {
        int j = nb[k];
        float ex = vb[j*3]-xi, ey = vb[j*3+1]-yi, ez = vb[j*3+2]-zi;
        float inv = 1.0f / fmaxf(sqrtf(ex*ex + ey*ey + ez*ez), 1e-12f);
        float th  = fmaxf((ex*dx + ey*dy + ez*dz) * inv, 0.0f);
        float fs  = g_FO[(size_t)(base + j)*2*DD + DD + d];
        m = fmaxf(m, th * fs);
    }
    bufsel(outid)[p*DD + d] = g_FO[(size_t)p*2*DD + d] + m;
}

/* ---------------- final: relu(concat(A,B,C) @ W_down + b_down) ------------ */
__global__ void final_kernel(const float* __restrict__ Wd,
                             const float* __restrict__ bd,
                             float* __restrict__ out) {
    __shared__ float sx[16*384];
    int r0 = blockIdx.x * 16;
    for (int idx = threadIdx.x; idx < 16*384; idx += blockDim.x) {
        int r = idx / 384, c = idx % 384;
        float v;
        if (c < 128)      v = g_bufA[(r0 + r)*DD + c];
        else if (c < 256) v = g_bufB[(r0 + r)*DD + (c - 128)];
        else              v = g_bufC[(r0 + r)*DD + (c - 256)];
        sx[idx] = v;
    }
    __syncthreads();
    int col = threadIdx.x;
    float acc[16];
    float bv = bd[col];
    #pragma unroll
    for (int r = 0; r < 16; ++r) acc[r] = bv;
    for (int k = 0; k < 384; ++k) {
        float w = Wd[k*256 + col];
        #pragma unroll
        for (int r = 0; r < 16; ++r) acc[r] += sx[r*384 + k] * w;
    }
    #pragma unroll
    for (int r = 0; r < 16; ++r)
        out[(size_t)(r0 + r)*256 + col] = fmaxf(acc[r], 0.0f);
}

/* ---------------- launch ------------------------------------------------- */
extern "C" void kernel_launch(void* const* d_in, const int* in_sizes, int n_in,
                              void* d_out, int out_size) {
    (void)in_sizes; (void)n_in; (void)out_size;
    const float* verts   = (const float*)d_in[0];
    const float* dirs_l  = (const float*)d_in[1];
    const float* dirs_m0 = (const float*)d_in[2];
    const float* W_m1    = (const float*)d_in[3];
    const float* b_m1    = (const float*)d_in[4];
    const float* dirs_m1 = (const float*)d_in[5];
    const float* dirs_g0 = (const float*)d_in[6];
    const float* W_g1    = (const float*)d_in[7];
    const float* b_g1    = (const float*)d_in[8];
    const float* dirs_g1 = (const float*)d_in[9];
    const float* W_g2    = (const float*)d_in[10];
    const float* b_g2    = (const float*)d_in[11];
    const float* dirs_g2 = (const float*)d_in[12];
    const float* g_l     = (const float*)d_in[13];
    const float* be_l    = (const float*)d_in[14];
    const float* g_m0    = (const float*)d_in[15];
    const float* be_m0   = (const float*)d_in[16];
    const float* g_m1    = (const float*)d_in[17];
    const float* be_m1   = (const float*)d_in[18];
    const float* g_g0    = (const float*)d_in[19];
    const float* be_g0   = (const float*)d_in[20];
    const float* g_g1    = (const float*)d_in[21];
    const float* be_g1   = (const float*)d_in[22];
    const float* g_g2    = (const float*)d_in[23];
    const float* be_g2   = (const float*)d_in[24];
    const float* W_down  = (const float*)d_in[25];
    const float* b_down  = (const float*)d_in[26];
    float* out = (float*)d_out;

    prep_kernel<<<1, 256>>>(dirs_l, dirs_m0, dirs_m1, dirs_g0, dirs_g1, dirs_g2);
    knn_kernel<<<ROWS, 256>>>(verts);
    surf_kernel<<<dim3(ROWS, 3), DD>>>(verts);

    stats_kernel<<<PART, DD>>>(0, 0);
    stats_kernel<<<PART, DD>>>(1, 1);
    stats_kernel<<<PART, DD>>>(2, 3);
    bnapply_kernel<<<PART, DD>>>(0, 0, g_l,  be_l);
    bnapply_kernel<<<PART, DD>>>(1, 1, g_m0, be_m0);
    bnapply_kernel<<<PART, DD>>>(2, 3, g_g0, be_g0);

    // medium scale layer 1
    gemm_kernel<<<ROWS/16, 256>>>(1, W_m1, b_m1);
    convlayer_kernel<<<ROWS, DD>>>(verts, 2, 20, 1);
    stats_kernel<<<PART, DD>>>(1, 2);
    bnapply_kernel<<<PART, DD>>>(1, 2, g_m1, be_m1);

    // global scale layer 1
    gemm_kernel<<<ROWS/16, 256>>>(2, W_g1, b_g1);
    convlayer_kernel<<<ROWS, DD>>>(verts, 4, 100, 2);
    stats_kernel<<<PART, DD>>>(2, 4);
    bnapply_kernel<<<PART, DD>>>(2, 4, g_g1, be_g1);

    // global scale layer 2
    gemm_kernel<<<ROWS/16, 256>>>(2, W_g2, b_g2);
    convlayer_kernel<<<ROWS, DD>>>(verts, 5, 100, 2);
    stats_kernel<<<PART, DD>>>(2, 5);
    bnapply_kernel<<<PART, DD>>>(2, 5, g_g2, be_g2);

    final_kernel<<<ROWS/16, 256>>>(W_down, b_down, out);
}

// round 10
// speedup vs baseline: 1.4328x; 1.4328x over previous
#include <cuda_runtime.h>
#include <math.h>

#define BB 4
#define NPTS 1024
#define ROWS (BB*NPTS)   /* 4096 */
#define DD 128
#define KG 100
#define PART 256         /* partial-sum blocks for BN stats */

/* ---------------- device scratch (no allocations allowed) ---------------- */
__device__ float  g_bufA[ROWS*DD];     // fm_l
__device__ float  g_bufB[ROWS*DD];     // fm_m chain (raw pre-BN values)
__device__ float  g_bufC[ROWS*DD];     // fm_g chain (raw pre-BN values)
__device__ float  g_FO[ROWS*2*DD];     // gemm output fo (fc|fs)
__device__ int    g_nbr[ROWS*KG];      // 100 nearest (sorted; prefixes = k=5/20)
__device__ float  g_dirs[6][3*DD];     // normalized dirs: l,m0,m1,g0,g1,g2
__device__ double g_ps [6][PART][DD];  // BN partial sums
__device__ double g_ps2[6][PART][DD];  // BN partial sumsq
__device__ float  g_bnsc[6][DD];       // folded BN scale
__device__ float  g_bnsh[6][DD];       // folded BN shift

__device__ __forceinline__ float* bufsel(int id) {
    return id == 0 ? g_bufA : (id == 1 ? g_bufB : g_bufC);
}

/* ---------------- prep: normalize direction matrices --------------------- */
__global__ void prep_kernel(const float* dl, const float* dm0, const float* dm1,
                            const float* dg0, const float* dg1, const float* dg2) {
    const float* src[6] = {dl, dm0, dm1, dg0, dg1, dg2};
    for (int t = threadIdx.x; t < 6*DD; t += blockDim.x) {
        int w = t / DD, c = t % DD;
        const float* s = src[w];
        float x = s[c], y = s[DD + c], z = s[2*DD + c];
        float inv = 1.0f / fmaxf(sqrtf(x*x + y*y + z*z), 1e-12f);
        g_dirs[w][c]        = x * inv;
        g_dirs[w][DD + c]   = y * inv;
        g_dirs[w][2*DD + c] = z * inv;
    }
}

/* ---------------- KNN: radix-select 102nd key + small bitonic ------------- */
/* One block (256 threads) per point. Distances kept in registers (4/thread).
   Radix-select (4 byte passes) finds the exact 102nd-smallest encoded
   distance; compact all candidates <= T (>=102, typically 102); sort 256
   padded slots by (dist,idx) -- exact top_k tie-breaking; emit ranks 1..100.
   All emitted indices are masked to [0,NPTS) as OOB defense. */
__global__ void knn_kernel(const float* __restrict__ verts) {
    __shared__ int hist[256];
    __shared__ unsigned long long ck[256];
    __shared__ int wsum[8];
    __shared__ int s_cnt, s_want;
    __shared__ unsigned int s_prefix;

    int p = blockIdx.x;
    int b = p >> 10, i = p & (NPTS - 1);
    const float* vb = verts + (size_t)b * NPTS * 3;
    int t = threadIdx.x;

    float xi = vb[i*3], yi = vb[i*3+1], zi = vb[i*3+2];
    float sqi = xi*xi + yi*yi + zi*zi;

    unsigned int u[4];
    #pragma unroll
    for (int v = 0; v < 4; ++v) {
        int j = t + 256 * v;
        float xj = vb[j*3], yj = vb[j*3+1], zj = vb[j*3+2];
        float sqj = xj*xj + yj*yj + zj*zj;
        float dot = xi*xj + yi*yj + zi*zj;
        float d   = sqi + sqj - 2.0f * dot;      // identical to reference formula
        unsigned int fb = __float_as_uint(d);
        u[v] = (fb & 0x80000000u) ? ~fb : (fb | 0x80000000u);  // order-preserving
    }

    if (t == 0) { s_cnt = 0; s_want = 102; s_prefix = 0u; }

    for (int shift = 24; shift >= 0; shift -= 8) {
        hist[t] = 0;
        __syncthreads();
        unsigned int pref = s_prefix;
        int want = s_want;
        #pragma unroll
        for (int v = 0; v < 4; ++v) {
            bool ok = (shift == 24) || ((u[v] >> (shift + 8)) == (pref >> (shift + 8)));
            if (ok) atomicAdd(&hist[(u[v] >> shift) & 255], 1);
        }
        __syncthreads();
        int val = hist[t];
        int x = val;
        int lane = t & 31, w = t >> 5;
        #pragma unroll
        for (int o = 1; o < 32; o <<= 1) {
            int y = __shfl_up_sync(0xffffffffu, x, o);
            if (lane >= o) x += y;
        }
        if (lane == 31) wsum[w] = x;
        __syncthreads();
        int base = 0;
        #pragma unroll
        for (int q = 0; q < 8; ++q) if (q < w) base += wsum[q];
        int incl = base + x, excl = incl - val;
        if (want > excl && want <= incl) {       // unique thread
            s_prefix = pref | ((unsigned)t << shift);
            s_want   = want - excl;
        }
        __syncthreads();
    }

    unsigned int T = s_prefix;                   // exact 102nd smallest key
    #pragma unroll
    for (int v = 0; v < 4; ++v) {
        if (u[v] <= T) {
            int pos = atomicAdd(&s_cnt, 1);
            if (pos < 256)
                ck[pos] = ((unsigned long long)u[v] << 32) | (unsigned)(t + 256 * v);
        }
    }
    __syncthreads();
    int cnt = s_cnt; if (cnt > 256) cnt = 256;
    if (t >= cnt) ck[t] = 0xFFFFFFFFFFFFFFFFull;
    __syncthreads();

    for (int kk = 2; kk <= 256; kk <<= 1) {
        for (int jj = kk >> 1; jj > 0; jj >>= 1) {
            int ixj = t ^ jj;
            if (ixj > t) {
                unsigned long long a = ck[t], c = ck[ixj];
                bool up = ((t & kk) == 0);
                if ((a > c) == up) { ck[t] = c; ck[ixj] = a; }
            }
            __syncthreads();
        }
    }
    if (t < KG)
        g_nbr[p*KG + t] = (int)(ck[1 + t] & (unsigned)(NPTS - 1));  // masked: OOB defense
}

/* ---------------- conv_surface: all three scales fused -------------------- */
__global__ void surf_kernel(const float* __restrict__ verts) {
    int p = blockIdx.x;
    int b = p >> 10, i = p & (NPTS - 1);
    const float* vb = verts + (size_t)b * NPTS * 3;
    int d = threadIdx.x;
    float lx = g_dirs[0][d], ly = g_dirs[0][DD+d], lz = g_dirs[0][2*DD+d];
    float mx = g_dirs[1][d], my = g_dirs[1][DD+d], mz = g_dirs[1][2*DD+d];
    float gx = g_dirs[3][d], gy = g_dirs[3][DD+d], gz = g_dirs[3][2*DD+d];
    float xi = vb[i*3], yi = vb[i*3+1], zi = vb[i*3+2];
    const int* nb = g_nbr + p*KG;
    float ml = 0.0f, mm = 0.0f, mg = 0.0f;       // max of relu >= 0
    for (int k = 0; k < KG; ++k) {
        int j = nb[k] & (NPTS - 1);
        float ex = vb[j*3]-xi, ey = vb[j*3+1]-yi, ez = vb[j*3+2]-zi;
        float inv = 1.0f / fmaxf(sqrtf(ex*ex + ey*ey + ez*ez), 1e-12f);
        float nx = ex*inv, ny = ey*inv, nz = ez*inv;
        mg = fmaxf(mg, nx*gx + ny*gy + nz*gz);
        if (k < 20) mm = fmaxf(mm, nx*mx + ny*my + nz*mz);
        if (k < 5)  ml = fmaxf(ml, nx*lx + ny*ly + nz*lz);
    }
    g_bufA[p*DD + d] = ml;
    g_bufB[p*DD + d] = mm;
    g_bufC[p*DD + d] = mg;
}

/* ---------------- BN stats (deterministic, 256-block grid) ---------------- */
__global__ void stats_kernel(int bufid, int slot) {
    const float* buf = bufsel(bufid);
    int d = threadIdx.x, blk = blockIdx.x;
    double s = 0.0, s2 = 0.0;
    int r0 = blk * (ROWS / PART);
    for (int r = r0; r < r0 + ROWS / PART; ++r) {
        float x = buf[r*DD + d];
        s += x; s2 += (double)x * x;
    }
    g_ps [slot][blk][d] = s;
    g_ps2[slot][blk][d] = s2;
}

/* ---------------- BN finalize: up to 3 slots -> sc/sh --------------------- */
__global__ void finalize_kernel(int sl0, const float* ga0, const float* bt0,
                                int sl1, const float* ga1, const float* bt1,
                                int sl2, const float* ga2, const float* bt2) {
    int which = blockIdx.x;
    int slot = (which == 0) ? sl0 : ((which == 1) ? sl1 : sl2);
    const float* g  = (which == 0) ? ga0 : ((which == 1) ? ga1 : ga2);
    const float* be = (which == 0) ? bt0 : ((which == 1) ? bt1 : bt2);
    if (slot < 0) return;
    int d = threadIdx.x;
    double s = 0.0, s2 = 0.0;
    for (int pb = 0; pb < PART; ++pb) { s += g_ps[slot][pb][d]; s2 += g_ps2[slot][pb][d]; }
    double mean = s / ROWS;
    float var = (float)(s2 / ROWS - mean * mean);
    float sc = rsqrtf(var + 1e-5f) * g[d];
    g_bnsc[slot][d] = sc;
    g_bnsh[slot][d] = be[d] - (float)mean * sc;
}

/* ---------------- GEMM (BN+relu fused on load of X) ----------------------- */
__global__ void gemm_kernel(int xid, int slot, const float* __restrict__ W,
                            const float* __restrict__ bias) {
    __shared__ float sx[16*DD];
    const float* X = bufsel(xid);
    int r0 = blockIdx.x * 16;
    for (int idx = threadIdx.x; idx < 16*DD; idx += blockDim.x) {
        int ch = idx & (DD - 1);
        float x = X[r0*DD + idx];
        sx[idx] = fmaxf(x * g_bnsc[slot][ch] + g_bnsh[slot][ch], 0.0f);
    }
    __syncthreads();
    int col = threadIdx.x;                 // 0..255
    float acc[16];
    float bv = bias[col];
    #pragma unroll
    for (int r = 0; r < 16; ++r) acc[r] = bv;
    for (int k = 0; k < DD; ++k) {
        float w = W[k*256 + col];
        #pragma unroll
        for (int r = 0; r < 16; ++r) acc[r] += sx[r*DD + k] * w;
    }
    #pragma unroll
    for (int r = 0; r < 16; ++r)
        g_FO[(size_t)(r0 + r)*2*DD + col] = acc[r];
}

/* ---------------- conv_layer combine: fc + max_k(theta*fs[nbr]) ----------- */
__global__ void convlayer_kernel(const float* __restrict__ verts,
                                 int dirslot, int K, int outid) {
    int p = blockIdx.x;
    int b = p >> 10, i = p & (NPTS - 1);
    const float* vb = verts + (size_t)b * NPTS * 3;
    int d = threadIdx.x;
    float dx = g_dirs[dirslot][d], dy = g_dirs[dirslot][DD + d], dz = g_dirs[dirslot][2*DD + d];
    float xi = vb[i*3], yi = vb[i*3+1], zi = vb[i*3+2];
    const int* nb = g_nbr + p*KG;
    int base = b * NPTS;
    float m = -3.4e38f;
    for (int k = 0; k < K; ++k) {
        int j = nb[k] & (NPTS - 1);
        float ex = vb[j*3]-xi, ey = vb[j*3+1]-yi, ez = vb[j*3+2]-zi;
        float inv = 1.0f / fmaxf(sqrtf(ex*ex + ey*ey + ez*ez), 1e-12f);
        float th  = fmaxf((ex*dx + ey*dy + ez*dz) * inv, 0.0f);
        float fs  = g_FO[(size_t)(base + j)*2*DD + DD + d];
        m = fmaxf(m, th * fs);
    }
    bufsel(outid)[p*DD + d] = g_FO[(size_t)p*2*DD + d] + m;
}

/* ---------------- final: relu(concat(bn(A),bn(B),bn(C)) @ Wd + bd) -------- */
__global__ void final_kernel(const float* __restrict__ Wd,
                             const float* __restrict__ bd,
                             float* __restrict__ out) {
    __shared__ float sx[16*384];
    int r0 = blockIdx.x * 16;
    for (int idx = threadIdx.x; idx < 16*384; idx += blockDim.x) {
        int r = idx / 384, c = idx % 384;
        int ch = c & (DD - 1);
        float v; int slot;
        if (c < 128)      { v = g_bufA[(r0 + r)*DD + ch]; slot = 0; }
        else if (c < 256) { v = g_bufB[(r0 + r)*DD + ch]; slot = 2; }
        else              { v = g_bufC[(r0 + r)*DD + ch]; slot = 5; }
        sx[idx] = fmaxf(v * g_bnsc[slot][ch] + g_bnsh[slot][ch], 0.0f);
    }
    __syncthreads();
    int col = threadIdx.x;
    float acc[16];
    float bv = bd[col];
    #pragma unroll
    for (int r = 0; r < 16; ++r) acc[r] = bv;
    for (int k = 0; k < 384; ++k) {
        float w = Wd[k*256 + col];
        #pragma unroll
        for (int r = 0; r < 16; ++r) acc[r] += sx[r*384 + k] * w;
    }
    #pragma unroll
    for (int r = 0; r < 16; ++r)
        out[(size_t)(r0 + r)*256 + col] = fmaxf(acc[r], 0.0f);
}

/* ---------------- launch ------------------------------------------------- */
extern "C" void kernel_launch(void* const* d_in, const int* in_sizes, int n_in,
                              void* d_out, int out_size) {
    (void)in_sizes; (void)n_in; (void)out_size;
    const float* verts   = (const float*)d_in[0];
    const float* dirs_l  = (const float*)d_in[1];
    const float* dirs_m0 = (const float*)d_in[2];
    const float* W_m1    = (const float*)d_in[3];
    const float* b_m1    = (const float*)d_in[4];
    const float* dirs_m1 = (const float*)d_in[5];
    const float* dirs_g0 = (const float*)d_in[6];
    const float* W_g1    = (const float*)d_in[7];
    const float* b_g1    = (const float*)d_in[8];
    const float* dirs_g1 = (const float*)d_in[9];
    const float* W_g2    = (const float*)d_in[10];
    const float* b_g2    = (const float*)d_in[11];
    const float* dirs_g2 = (const float*)d_in[12];
    const float* g_l     = (const float*)d_in[13];
    const float* be_l    = (const float*)d_in[14];
    const float* g_m0    = (const float*)d_in[15];
    const float* be_m0   = (const float*)d_in[16];
    const float* g_m1    = (const float*)d_in[17];
    const float* be_m1   = (const float*)d_in[18];
    const float* g_g0    = (const float*)d_in[19];
    const float* be_g0   = (const float*)d_in[20];
    const float* g_g1    = (const float*)d_in[21];
    const float* be_g1   = (const float*)d_in[22];
    const float* g_g2    = (const float*)d_in[23];
    const float* be_g2   = (const float*)d_in[24];
    const float* W_down  = (const float*)d_in[25];
    const float* b_down  = (const float*)d_in[26];
    float* out = (float*)d_out;

    prep_kernel<<<1, 256>>>(dirs_l, dirs_m0, dirs_m1, dirs_g0, dirs_g1, dirs_g2);
    knn_kernel<<<ROWS, 256>>>(verts);
    surf_kernel<<<ROWS, DD>>>(verts);

    stats_kernel<<<PART, DD>>>(0, 0);
    stats_kernel<<<PART, DD>>>(1, 1);
    stats_kernel<<<PART, DD>>>(2, 3);
    finalize_kernel<<<3, DD>>>(0, g_l, be_l, 1, g_m0, be_m0, 3, g_g0, be_g0);

    // medium scale layer 1
    gemm_kernel<<<ROWS/16, 256>>>(1, 1, W_m1, b_m1);
    convlayer_kernel<<<ROWS, DD>>>(verts, 2, 20, 1);
    stats_kernel<<<PART, DD>>>(1, 2);

    // global scale layer 1
    gemm_kernel<<<ROWS/16, 256>>>(2, 3, W_g1, b_g1);
    convlayer_kernel<<<ROWS, DD>>>(verts, 4, 100, 2);
    stats_kernel<<<PART, DD>>>(2, 4);
    finalize_kernel<<<2, DD>>>(2, g_m1, be_m1, 4, g_g1, be_g1, -1, (const float*)0, (const float*)0);

    // global scale layer 2
    gemm_kernel<<<ROWS/16, 256>>>(2, 4, W_g2, b_g2);
    convlayer_kernel<<<ROWS, DD>>>(verts, 5, 100, 2);
    stats_kernel<<<PART, DD>>>(2, 5);
    finalize_kernel<<<1, DD>>>(5, g_g2, be_g2, -1, (const float*)0, (const float*)0, -1, (const float*)0, (const float*)0);

    final_kernel<<<ROWS/16, 256>>>(W_down, b_down, out);
}

// round 15
// speedup vs baseline: 1.4559x; 1.0162x over previous
#include <cuda_runtime.h>
#include <math.h>

#define BB 4
#define NPTS 1024
#define ROWS (BB*NPTS)   /* 4096 */
#define DD 128
#define KG 100
#define PART 256         /* partial-sum blocks for BN stats */

/* ---------------- device scratch (no allocations allowed) ---------------- */
__device__ float  g_bufA[ROWS*DD];     // fm_l
__device__ float  g_bufB[ROWS*DD];     // fm_m chain (raw pre-BN values)
__device__ float  g_bufC[ROWS*DD];     // fm_g chain (raw pre-BN values)
__device__ float  g_FO[ROWS*2*DD];     // gemm output fo (fc|fs)
__device__ int    g_nbr[ROWS*KG];      // 100 nearest (rank order; prefixes = k=5/20)
__device__ float  g_dirs[6][3*DD];     // normalized dirs: l,m0,m1,g0,g1,g2
__device__ double g_ps [6][PART][DD];  // BN partial sums
__device__ double g_ps2[6][PART][DD];  // BN partial sumsq
__device__ float  g_bnsc[6][DD];       // folded BN scale
__device__ float  g_bnsh[6][DD];       // folded BN shift

__device__ __forceinline__ float* bufsel(int id) {
    return id == 0 ? g_bufA : (id == 1 ? g_bufB : g_bufC);
}

/* ---------------- prep: normalize direction matrices --------------------- */
__global__ void prep_kernel(const float* dl, const float* dm0, const float* dm1,
                            const float* dg0, const float* dg1, const float* dg2) {
    const float* src[6] = {dl, dm0, dm1, dg0, dg1, dg2};
    for (int t = threadIdx.x; t < 6*DD; t += blockDim.x) {
        int w = t / DD, c = t % DD;
        const float* s = src[w];
        float x = s[c], y = s[DD + c], z = s[2*DD + c];
        float inv = 1.0f / fmaxf(sqrtf(x*x + y*y + z*z), 1e-12f);
        g_dirs[w][c]        = x * inv;
        g_dirs[w][DD + c]   = y * inv;
        g_dirs[w][2*DD + c] = z * inv;
    }
}

/* ---------------- KNN: 3-pass radix prefix-select + exact rank count ------ */
/* One block (256 threads) per point; 4 keys/thread in registers.
   3 byte passes (per-warp hists) find the 24-bit prefix T of the 102nd
   smallest encoded distance (prefix order coarsens key order, so the 102nd
   prefix == prefix of the 102nd key). Compact all keys with prefix <= T
   (>=102 candidates), then each candidate counts smaller 64-bit (dist,idx)
   keys among candidates -> exact rank with top_k tie-breaking. Ranks 1..100
   are written directly; no sort needed (downstream is order-invariant max,
   and prefix sets {5},{20},{100} are rank-prefix sets). */
__global__ void knn_kernel(const float* __restrict__ verts) {
    __shared__ int hist[8][256];
    __shared__ unsigned long long ck[256];
    __shared__ int wsum[8];
    __shared__ int s_cnt, s_want;
    __shared__ unsigned int s_prefix;

    int p = blockIdx.x;
    int b = p >> 10, i = p & (NPTS - 1);
    const float* vb = verts + (size_t)b * NPTS * 3;
    int t = threadIdx.x;
    int lane = t & 31, w = t >> 5;

    float xi = vb[i*3], yi = vb[i*3+1], zi = vb[i*3+2];
    float sqi = xi*xi + yi*yi + zi*zi;

    unsigned int u[4];
    #pragma unroll
    for (int v = 0; v < 4; ++v) {
        int j = t + 256 * v;
        float xj = vb[j*3], yj = vb[j*3+1], zj = vb[j*3+2];
        float sqj = xj*xj + yj*yj + zj*zj;
        float dot = xi*xj + yi*yj + zi*zj;
        float d   = sqi + sqj - 2.0f * dot;      // identical to reference formula
        unsigned int fb = __float_as_uint(d);
        u[v] = (fb & 0x80000000u) ? ~fb : (fb | 0x80000000u);  // order-preserving
    }

    if (t == 0) { s_cnt = 0; s_want = 102; s_prefix = 0u; }

    for (int shift = 24; shift >= 8; shift -= 8) {
        #pragma unroll
        for (int q = 0; q < 8; ++q) hist[q][t] = 0;
        __syncthreads();                          // also publishes s_* init
        unsigned int pref = s_prefix;
        int want = s_want;
        #pragma unroll
        for (int v = 0; v < 4; ++v) {
            bool ok = (shift == 24) || ((u[v] >> (shift + 8)) == (pref >> (shift + 8)));
            if (ok) atomicAdd(&hist[w][(u[v] >> shift) & 255], 1);
        }
        __syncthreads();
        int val = hist[0][t] + hist[1][t] + hist[2][t] + hist[3][t]
                + hist[4][t] + hist[5][t] + hist[6][t] + hist[7][t];
        int x = val;
        #pragma unroll
        for (int o = 1; o < 32; o <<= 1) {
            int y = __shfl_up_sync(0xffffffffu, x, o);
            if (lane >= o) x += y;
        }
        if (lane == 31) wsum[w] = x;
        __syncthreads();
        int base = 0;
        #pragma unroll
        for (int q = 0; q < 8; ++q) if (q < w) base += wsum[q];
        int incl = base + x, excl = incl - val;
        if (want > excl && want <= incl) {        // unique winner thread
            s_prefix = pref | ((unsigned)t << shift);
            s_want   = want - excl;
        }
        __syncthreads();
    }

    unsigned int Tpref = s_prefix >> 8;           // 24-bit prefix of 102nd key
    #pragma unroll
    for (int v = 0; v < 4; ++v) {
        if ((u[v] >> 8) <= Tpref) {
            int pos = atomicAdd(&s_cnt, 1);
            if (pos < 256)
                ck[pos] = ((unsigned long long)u[v] << 32) | (unsigned)(t + 256 * v);
        }
    }
    __syncthreads();
    int cnt = s_cnt; if (cnt > 256) cnt = 256;

    if (t < cnt) {
        unsigned long long k = ck[t];
        int r = 0;
        for (int q = 0; q < cnt; ++q) r += (ck[q] < k);   // broadcast smem reads
        if (r >= 1 && r <= KG)
            g_nbr[p*KG + (r - 1)] = (int)(k & (unsigned)(NPTS - 1)); // masked: OOB defense
    }
}

/* ---------------- conv_surface: all three scales fused -------------------- */
__global__ void surf_kernel(const float* __restrict__ verts) {
    int p = blockIdx.x;
    int b = p >> 10, i = p & (NPTS - 1);
    const float* vb = verts + (size_t)b * NPTS * 3;
    int d = threadIdx.x;
    float lx = g_dirs[0][d], ly = g_dirs[0][DD+d], lz = g_dirs[0][2*DD+d];
    float mx = g_dirs[1][d], my = g_dirs[1][DD+d], mz = g_dirs[1][2*DD+d];
    float gx = g_dirs[3][d], gy = g_dirs[3][DD+d], gz = g_dirs[3][2*DD+d];
    float xi = vb[i*3], yi = vb[i*3+1], zi = vb[i*3+2];
    const int* nb = g_nbr + p*KG;
    float ml = 0.0f, mm = 0.0f, mg = 0.0f;       // max of relu >= 0
    #pragma unroll 4
    for (int k = 0; k < KG; ++k) {
        int j = nb[k] & (NPTS - 1);
        float ex = vb[j*3]-xi, ey = vb[j*3+1]-yi, ez = vb[j*3+2]-zi;
        float inv = 1.0f / fmaxf(sqrtf(ex*ex + ey*ey + ez*ez), 1e-12f);
        float nx = ex*inv, ny = ey*inv, nz = ez*inv;
        mg = fmaxf(mg, nx*gx + ny*gy + nz*gz);
        if (k < 20) mm = fmaxf(mm, nx*mx + ny*my + nz*mz);
        if (k < 5)  ml = fmaxf(ml, nx*lx + ny*ly + nz*lz);
    }
    g_bufA[p*DD + d] = ml;
    g_bufB[p*DD + d] = mm;
    g_bufC[p*DD + d] = mg;
}

/* ---------------- BN stats (deterministic; batched variant) --------------- */
__device__ __forceinline__ void stats_body(const float* buf, int slot) {
    int d = threadIdx.x, blk = blockIdx.x;
    double s = 0.0, s2 = 0.0;
    int r0 = blk * (ROWS / PART);
    #pragma unroll 4
    for (int r = r0; r < r0 + ROWS / PART; ++r) {
        float x = buf[r*DD + d];
        s += x; s2 += (double)x * x;
    }
    g_ps [slot][blk][d] = s;
    g_ps2[slot][blk][d] = s2;
}

__global__ void stats_kernel(int bufid, int slot) {
    stats_body(bufsel(bufid), slot);
}

__global__ void stats3_kernel() {                 // slots 0,1,3 from A,B,C
    int which = blockIdx.y;
    int bufid = which;
    int slot  = (which == 2) ? 3 : which;
    stats_body(bufsel(bufid), slot);
}

/* ---------------- BN finalize: up to 3 slots -> sc/sh --------------------- */
__global__ void finalize_kernel(int sl0, const float* ga0, const float* bt0,
                                int sl1, const float* ga1, const float* bt1,
                                int sl2, const float* ga2, const float* bt2) {
    int which = blockIdx.x;
    int slot = (which == 0) ? sl0 : ((which == 1) ? sl1 : sl2);
    const float* g  = (which == 0) ? ga0 : ((which == 1) ? ga1 : ga2);
    const float* be = (which == 0) ? bt0 : ((which == 1) ? bt1 : bt2);
    if (slot < 0) return;
    int d = threadIdx.x;
    double s = 0.0, s2 = 0.0;
    for (int pb = 0; pb < PART; ++pb) { s += g_ps[slot][pb][d]; s2 += g_ps2[slot][pb][d]; }
    double mean = s / ROWS;
    float var = (float)(s2 / ROWS - mean * mean);
    float sc = rsqrtf(var + 1e-5f) * g[d];
    g_bnsc[slot][d] = sc;
    g_bnsh[slot][d] = be[d] - (float)mean * sc;
}

/* ---------------- GEMM (BN+relu fused on load of X) ----------------------- */
__global__ void gemm_kernel(int xid, int slot, const float* __restrict__ W,
                            const float* __restrict__ bias) {
    __shared__ float sx[16*DD];
    const float* X = bufsel(xid);
    int r0 = blockIdx.x * 16;
    for (int idx = threadIdx.x; idx < 16*DD; idx += blockDim.x) {
        int ch = idx & (DD - 1);
        float x = X[r0*DD + idx];
        sx[idx] = fmaxf(x * g_bnsc[slot][ch] + g_bnsh[slot][ch], 0.0f);
    }
    __syncthreads();
    int col = threadIdx.x;                 // 0..255
    float acc[16];
    float bv = bias[col];
    #pragma unroll
    for (int r = 0; r < 16; ++r) acc[r] = bv;
    for (int k = 0; k < DD; ++k) {
        float w = W[k*256 + col];
        #pragma unroll
        for (int r = 0; r < 16; ++r) acc[r] += sx[r*DD + k] * w;
    }
    #pragma unroll
    for (int r = 0; r < 16; ++r)
        g_FO[(size_t)(r0 + r)*2*DD + col] = acc[r];
}

/* ---------------- conv_layer combine: fc + max_k(theta*fs[nbr]) ----------- */
template <int K>
__global__ void convlayer_kernel(const float* __restrict__ verts,
                                 int dirslot, int outid) {
    int p = blockIdx.x;
    int b = p >> 10, i = p & (NPTS - 1);
    const float* vb = verts + (size_t)b * NPTS * 3;
    int d = threadIdx.x;
    float dx = g_dirs[dirslot][d], dy = g_dirs[dirslot][DD + d], dz = g_dirs[dirslot][2*DD + d];
    float xi = vb[i*3], yi = vb[i*3+1], zi = vb[i*3+2];
    const int* nb = g_nbr + p*KG;
    int base = b * NPTS;
    float m = -3.4e38f;
    #pragma unroll 4
    for (int k = 0; k < K; ++k) {
        int j = nb[k] & (NPTS - 1);
        float ex = vb[j*3]-xi, ey = vb[j*3+1]-yi, ez = vb[j*3+2]-zi;
        float inv = 1.0f / fmaxf(sqrtf(ex*ex + ey*ey + ez*ez), 1e-12f);
        float th  = fmaxf((ex*dx + ey*dy + ez*dz) * inv, 0.0f);
        float fs  = g_FO[(size_t)(base + j)*2*DD + DD + d];
        m = fmaxf(m, th * fs);
    }
    bufsel(outid)[p*DD + d] = g_FO[(size_t)p*2*DD + d] + m;
}

/* ---------------- final: relu(concat(bn(A),bn(B),bn(C)) @ Wd + bd) -------- */
__global__ void final_kernel(const float* __restrict__ Wd,
                             const float* __restrict__ bd,
                             float* __restrict__ out) {
    __shared__ float sx[16*384];
    int r0 = blockIdx.x * 16;
    for (int idx = threadIdx.x; idx < 16*384; idx += blockDim.x) {
        int r = idx / 384, c = idx % 384;
        int ch = c & (DD - 1);
        float v; int slot;
        if (c < 128)      { v = g_bufA[(r0 + r)*DD + ch]; slot = 0; }
        else if (c < 256) { v = g_bufB[(r0 + r)*DD + ch]; slot = 2; }
        else              { v = g_bufC[(r0 + r)*DD + ch]; slot = 5; }
        sx[idx] = fmaxf(v * g_bnsc[slot][ch] + g_bnsh[slot][ch], 0.0f);
    }
    __syncthreads();
    int col = threadIdx.x;
    float acc[16];
    float bv = bd[col];
    #pragma unroll
    for (int r = 0; r < 16; ++r) acc[r] = bv;
    for (int k = 0; k < 384; ++k) {
        float w = Wd[k*256 + col];
        #pragma unroll
        for (int r = 0; r < 16; ++r) acc[r] += sx[r*384 + k] * w;
    }
    #pragma unroll
    for (int r = 0; r < 16; ++r)
        out[(size_t)(r0 + r)*256 + col] = fmaxf(acc[r], 0.0f);
}

/* ---------------- launch ------------------------------------------------- */
extern "C" void kernel_launch(void* const* d_in, const int* in_sizes, int n_in,
                              void* d_out, int out_size) {
    (void)in_sizes; (void)n_in; (void)out_size;
    const float* verts   = (const float*)d_in[0];
    const float* dirs_l  = (const float*)d_in[1];
    const float* dirs_m0 = (const float*)d_in[2];
    const float* W_m1    = (const float*)d_in[3];
    const float* b_m1    = (const float*)d_in[4];
    const float* dirs_m1 = (const float*)d_in[5];
    const float* dirs_g0 = (const float*)d_in[6];
    const float* W_g1    = (const float*)d_in[7];
    const float* b_g1    = (const float*)d_in[8];
    const float* dirs_g1 = (const float*)d_in[9];
    const float* W_g2    = (const float*)d_in[10];
    const float* b_g2    = (const float*)d_in[11];
    const float* dirs_g2 = (const float*)d_in[12];
    const float* g_l     = (const float*)d_in[13];
    const float* be_l    = (const float*)d_in[14];
    const float* g_m0    = (const float*)d_in[15];
    const float* be_m0   = (const float*)d_in[16];
    const float* g_m1    = (const float*)d_in[17];
    const float* be_m1   = (const float*)d_in[18];
    const float* g_g0    = (const float*)d_in[19];
    const float* be_g0   = (const float*)d_in[20];
    const float* g_g1    = (const float*)d_in[21];
    const float* be_g1   = (const float*)d_in[22];
    const float* g_g2    = (const float*)d_in[23];
    const float* be_g2   = (const float*)d_in[24];
    const float* W_down  = (const float*)d_in[25];
    const float* b_down  = (const float*)d_in[26];
    float* out = (float*)d_out;

    prep_kernel<<<1, 256>>>(dirs_l, dirs_m0, dirs_m1, dirs_g0, dirs_g1, dirs_g2);
    knn_kernel<<<ROWS, 256>>>(verts);
    surf_kernel<<<ROWS, DD>>>(verts);

    stats3_kernel<<<dim3(PART, 3), DD>>>();
    finalize_kernel<<<3, DD>>>(0, g_l, be_l, 1, g_m0, be_m0, 3, g_g0, be_g0);

    // medium scale layer 1
    gemm_kernel<<<ROWS/16, 256>>>(1, 1, W_m1, b_m1);
    convlayer_kernel<20><<<ROWS, DD>>>(verts, 2, 1);
    stats_kernel<<<PART, DD>>>(1, 2);

    // global scale layer 1
    gemm_kernel<<<ROWS/16, 256>>>(2, 3, W_g1, b_g1);
    convlayer_kernel<100><<<ROWS, DD>>>(verts, 4, 2);
    stats_kernel<<<PART, DD>>>(2, 4);
    finalize_kernel<<<2, DD>>>(2, g_m1, be_m1, 4, g_g1, be_g1, -1, (const float*)0, (const float*)0);

    // global scale layer 2
    gemm_kernel<<<ROWS/16, 256>>>(2, 4, W_g2, b_g2);
    convlayer_kernel<100><<<ROWS, DD>>>(verts, 5, 2);
    stats_kernel<<<PART, DD>>>(2, 5);
    finalize_kernel<<<1, DD>>>(5, g_g2, be_g2, -1, (const float*)0, (const float*)0, -1, (const float*)0, (const float*)0);

    final_kernel<<<ROWS/16, 256>>>(W_down, b_down, out);
}

// round 16
// speedup vs baseline: 2.1474x; 1.4749x over previous
#include <cuda_runtime.h>
#include <math.h>

#define BB 4
#define NPTS 1024
#define ROWS (BB*NPTS)   /* 4096 */
#define DD 128
#define KG 100
#define PART 256         /* partial-sum blocks for BN stats */

/* ---------------- device scratch (no allocations allowed) ---------------- */
__device__ float  g_bufA[ROWS*DD];     // fm_l
__device__ float  g_bufB[ROWS*DD];     // fm_m chain (raw pre-BN values)
__device__ float  g_bufC[ROWS*DD];     // fm_g chain (raw pre-BN values)
__device__ float  g_FO[ROWS*2*DD];     // gemm output fo (fc|fs)
__device__ int    g_nbr[ROWS*KG];      // 100 nearest (rank order; prefixes = k=5/20)
__device__ float4 g_nd[ROWS*KG];       // precomputed normalized neighbor dirs
__device__ float  g_dirs[6][3*DD];     // normalized dirs: l,m0,m1,g0,g1,g2
__device__ double g_ps [6][PART][DD];  // BN partial sums
__device__ double g_ps2[6][PART][DD];  // BN partial sumsq
__device__ float  g_bnsc[6][DD];       // folded BN scale
__device__ float  g_bnsh[6][DD];       // folded BN shift

__device__ __forceinline__ float* bufsel(int id) {
    return id == 0 ? g_bufA : (id == 1 ? g_bufB : g_bufC);
}

/* ---------------- prep: normalize direction matrices --------------------- */
__global__ void prep_kernel(const float* dl, const float* dm0, const float* dm1,
                            const float* dg0, const float* dg1, const float* dg2) {
    const float* src[6] = {dl, dm0, dm1, dg0, dg1, dg2};
    for (int t = threadIdx.x; t < 6*DD; t += blockDim.x) {
        int w = t / DD, c = t % DD;
        const float* s = src[w];
        float x = s[c], y = s[DD + c], z = s[2*DD + c];
        float inv = 1.0f / fmaxf(sqrtf(x*x + y*y + z*z), 1e-12f);
        g_dirs[w][c]        = x * inv;
        g_dirs[w][DD + c]   = y * inv;
        g_dirs[w][2*DD + c] = z * inv;
    }
}

/* ---------------- KNN: 3-pass radix prefix-select + exact rank count ------ */
/* One block (256 threads) per point; 4 keys/thread in registers.
   3 byte passes find the 24-bit prefix of the 102nd-smallest encoded
   distance; compact candidates (prefix <= T), rank-count them exactly
   (top_k tie-break preserved), and the writer thread ALSO emits the
   normalized neighbor direction (layer-independent geometry) so the
   downstream gather kernels never touch vertices again. Histogram uses
   match_any leader aggregation to kill same-address ATOMS serialization. */
__global__ void knn_kernel(const float* __restrict__ verts) {
    __shared__ int hist[8][256];
    __shared__ unsigned long long ck[256];
    __shared__ int wsum[8];
    __shared__ int s_cnt, s_want;
    __shared__ unsigned int s_prefix;

    int p = blockIdx.x;
    int b = p >> 10, i = p & (NPTS - 1);
    const float* vb = verts + (size_t)b * NPTS * 3;
    int t = threadIdx.x;
    int lane = t & 31, w = t >> 5;

    float xi = vb[i*3], yi = vb[i*3+1], zi = vb[i*3+2];
    float sqi = xi*xi + yi*yi + zi*zi;

    unsigned int u[4];
    #pragma unroll
    for (int v = 0; v < 4; ++v) {
        int j = t + 256 * v;
        float xj = vb[j*3], yj = vb[j*3+1], zj = vb[j*3+2];
        float sqj = xj*xj + yj*yj + zj*zj;
        float dot = xi*xj + yi*yj + zi*zj;
        float d   = sqi + sqj - 2.0f * dot;      // identical to reference formula
        unsigned int fb = __float_as_uint(d);
        u[v] = (fb & 0x80000000u) ? ~fb : (fb | 0x80000000u);  // order-preserving
    }

    if (t == 0) { s_cnt = 0; s_want = 102; s_prefix = 0u; }

    for (int shift = 24; shift >= 8; shift -= 8) {
        #pragma unroll
        for (int q = 0; q < 8; ++q) hist[q][t] = 0;
        __syncthreads();                          // also publishes s_* init
        unsigned int pref = s_prefix;
        int want = s_want;
        #pragma unroll
        for (int v = 0; v < 4; ++v) {
            bool ok = (shift == 24) || ((u[v] >> (shift + 8)) == (pref >> (shift + 8)));
            unsigned int bin = (u[v] >> shift) & 255u;
            unsigned int key = ok ? bin : 0xFFFFFFFFu;
            unsigned int mm = __match_any_sync(0xFFFFFFFFu, key);  // warp converged here
            if (ok) {
                int leader = __ffs(mm) - 1;
                if (lane == leader) atomicAdd(&hist[w][bin], __popc(mm));
            }
        }
        __syncthreads();
        int val = hist[0][t] + hist[1][t] + hist[2][t] + hist[3][t]
                + hist[4][t] + hist[5][t] + hist[6][t] + hist[7][t];
        int x = val;
        #pragma unroll
        for (int o = 1; o < 32; o <<= 1) {
            int y = __shfl_up_sync(0xffffffffu, x, o);
            if (lane >= o) x += y;
        }
        if (lane == 31) wsum[w] = x;
        __syncthreads();
        int base = 0;
        #pragma unroll
        for (int q = 0; q < 8; ++q) if (q < w) base += wsum[q];
        int incl = base + x, excl = incl - val;
        if (want > excl && want <= incl) {        // unique winner thread
            s_prefix = pref | ((unsigned)t << shift);
            s_want   = want - excl;
        }
        __syncthreads();
    }

    unsigned int Tpref = s_prefix >> 8;           // 24-bit prefix of 102nd key
    #pragma unroll
    for (int v = 0; v < 4; ++v) {
        if ((u[v] >> 8) <= Tpref) {
            int pos = atomicAdd(&s_cnt, 1);
            if (pos < 256)
                ck[pos] = ((unsigned long long)u[v] << 32) | (unsigned)(t + 256 * v);
        }
    }
    __syncthreads();
    int cnt = s_cnt; if (cnt > 256) cnt = 256;

    if (t < cnt) {
        unsigned long long k = ck[t];
        int r = 0;
        for (int q = 0; q < cnt; ++q) r += (ck[q] < k);   // broadcast smem reads
        if (r >= 1 && r <= KG) {
            int j = (int)(k & (unsigned)(NPTS - 1));      // masked: OOB defense
            g_nbr[p*KG + (r - 1)] = j;
            float ex = vb[j*3]   - xi;
            float ey = vb[j*3+1] - yi;
            float ez = vb[j*3+2] - zi;
            float inv = 1.0f / fmaxf(sqrtf(ex*ex + ey*ey + ez*ez), 1e-12f);
            g_nd[p*KG + (r - 1)] = make_float4(ex*inv, ey*inv, ez*inv, 0.0f);
        }
    }
}

/* ---------------- conv_surface: all three scales fused, nd-based ---------- */
__global__ void surf_kernel() {
    int p = blockIdx.x;
    int d = threadIdx.x;
    float lx = g_dirs[0][d], ly = g_dirs[0][DD+d], lz = g_dirs[0][2*DD+d];
    float mx = g_dirs[1][d], my = g_dirs[1][DD+d], mz = g_dirs[1][2*DD+d];
    float gx = g_dirs[3][d], gy = g_dirs[3][DD+d], gz = g_dirs[3][2*DD+d];
    const float4* nd = g_nd + p*KG;
    float ml = 0.0f, mm = 0.0f, mg = 0.0f;       // max of relu >= 0
    #pragma unroll 4
    for (int k = 0; k < KG; ++k) {
        float4 n = nd[k];                         // broadcast LDG.128
        mg = fmaxf(mg, n.x*gx + n.y*gy + n.z*gz);
        if (k < 20) mm = fmaxf(mm, n.x*mx + n.y*my + n.z*mz);
        if (k < 5)  ml = fmaxf(ml, n.x*lx + n.y*ly + n.z*lz);
    }
    g_bufA[p*DD + d] = ml;
    g_bufB[p*DD + d] = mm;
    g_bufC[p*DD + d] = mg;
}

/* ---------------- BN stats (fp32 partials; deterministic) ------------------ */
__device__ __forceinline__ void stats_body(const float* buf, int slot) {
    int d = threadIdx.x, blk = blockIdx.x;
    float s = 0.0f, s2 = 0.0f;
    int r0 = blk * (ROWS / PART);
    #pragma unroll 4
    for (int r = r0; r < r0 + ROWS / PART; ++r) {
        float x = buf[r*DD + d];
        s += x; s2 = fmaf(x, x, s2);
    }
    g_ps [slot][blk][d] = (double)s;
    g_ps2[slot][blk][d] = (double)s2;
}

__global__ void stats_kernel(int bufid, int slot) {
    stats_body(bufsel(bufid), slot);
}

__global__ void stats3_kernel() {                 // slots 0,1,3 from A,B,C
    int which = blockIdx.y;
    int bufid = which;
    int slot  = (which == 2) ? 3 : which;
    stats_body(bufsel(bufid), slot);
}

/* ---------------- BN finalize: up to 3 slots -> sc/sh --------------------- */
__global__ void finalize_kernel(int sl0, const float* ga0, const float* bt0,
                                int sl1, const float* ga1, const float* bt1,
                                int sl2, const float* ga2, const float* bt2) {
    int which = blockIdx.x;
    int slot = (which == 0) ? sl0 : ((which == 1) ? sl1 : sl2);
    const float* g  = (which == 0) ? ga0 : ((which == 1) ? ga1 : ga2);
    const float* be = (which == 0) ? bt0 : ((which == 1) ? bt1 : bt2);
    if (slot < 0) return;
    int d = threadIdx.x;
    double s = 0.0, s2 = 0.0;
    for (int pb = 0; pb < PART; ++pb) { s += g_ps[slot][pb][d]; s2 += g_ps2[slot][pb][d]; }
    double mean = s / ROWS;
    float var = (float)(s2 / ROWS - mean * mean);
    float sc = rsqrtf(var + 1e-5f) * g[d];
    g_bnsc[slot][d] = sc;
    g_bnsh[slot][d] = be[d] - (float)mean * sc;
}

/* ---------------- GEMM (BN+relu fused on load of X) ----------------------- */
__global__ void gemm_kernel(int xid, int slot, const float* __restrict__ W,
                            const float* __restrict__ bias) {
    __shared__ float sx[16*DD];
    const float* X = bufsel(xid);
    int r0 = blockIdx.x * 16;
    for (int idx = threadIdx.x; idx < 16*DD; idx += blockDim.x) {
        int ch = idx & (DD - 1);
        float x = X[r0*DD + idx];
        sx[idx] = fmaxf(x * g_bnsc[slot][ch] + g_bnsh[slot][ch], 0.0f);
    }
    __syncthreads();
    int col = threadIdx.x;                 // 0..255
    float acc[16];
    float bv = bias[col];
    #pragma unroll
    for (int r = 0; r < 16; ++r) acc[r] = bv;
    for (int k = 0; k < DD; ++k) {
        float w = W[k*256 + col];
        #pragma unroll
        for (int r = 0; r < 16; ++r) acc[r] += sx[r*DD + k] * w;
    }
    #pragma unroll
    for (int r = 0; r < 16; ++r)
        g_FO[(size_t)(r0 + r)*2*DD + col] = acc[r];
}

/* ---------------- conv_layer combine: fc + max_k(theta*fs[nbr]) ----------- */
template <int K>
__global__ void convlayer_kernel(int dirslot, int outid) {
    int p = blockIdx.x;
    int b = p >> 10;
    int d = threadIdx.x;
    float dx = g_dirs[dirslot][d], dy = g_dirs[dirslot][DD + d], dz = g_dirs[dirslot][2*DD + d];
    const int* nb = g_nbr + p*KG;
    const float4* nd = g_nd + p*KG;
    int base = b * NPTS;
    float m = -3.4e38f;
    #pragma unroll 4
    for (int k = 0; k < K; ++k) {
        float4 n = nd[k];                         // broadcast LDG.128
        int j = nb[k] & (NPTS - 1);
        float th = fmaxf(n.x*dx + n.y*dy + n.z*dz, 0.0f);
        float fs = g_FO[(size_t)(base + j)*2*DD + DD + d];
        m = fmaxf(m, th * fs);
    }
    bufsel(outid)[p*DD + d] = g_FO[(size_t)p*2*DD + d] + m;
}

/* ---------------- final: relu(concat(bn(A),bn(B),bn(C)) @ Wd + bd) -------- */
__global__ void final_kernel(const float* __restrict__ Wd,
                             const float* __restrict__ bd,
                             float* __restrict__ out) {
    __shared__ float sx[16*384];
    int r0 = blockIdx.x * 16;
    for (int idx = threadIdx.x; idx < 16*384; idx += blockDim.x) {
        int r = idx / 384, c = idx % 384;
        int ch = c & (DD - 1);
        float v; int slot;
        if (c < 128)      { v = g_bufA[(r0 + r)*DD + ch]; slot = 0; }
        else if (c < 256) { v = g_bufB[(r0 + r)*DD + ch]; slot = 2; }
        else              { v = g_bufC[(r0 + r)*DD + ch]; slot = 5; }
        sx[idx] = fmaxf(v * g_bnsc[slot][ch] + g_bnsh[slot][ch], 0.0f);
    }
    __syncthreads();
    int col = threadIdx.x;
    float acc[16];
    float bv = bd[col];
    #pragma unroll
    for (int r = 0; r < 16; ++r) acc[r] = bv;
    for (int k = 0; k < 384; ++k) {
        float w = Wd[k*256 + col];
        #pragma unroll
        for (int r = 0; r < 16; ++r) acc[r] += sx[r*384 + k] * w;
    }
    #pragma unroll
    for (int r = 0; r < 16; ++r)
        out[(size_t)(r0 + r)*256 + col] = fmaxf(acc[r], 0.0f);
}

/* ---------------- launch ------------------------------------------------- */
extern "C" void kernel_launch(void* const* d_in, const int* in_sizes, int n_in,
                              void* d_out, int out_size) {
    (void)in_sizes; (void)n_in; (void)out_size;
    const float* verts   = (const float*)d_in[0];
    const float* dirs_l  = (const float*)d_in[1];
    const float* dirs_m0 = (const float*)d_in[2];
    const float* W_m1    = (const float*)d_in[3];
    const float* b_m1    = (const float*)d_in[4];
    const float* dirs_m1 = (const float*)d_in[5];
    const float* dirs_g0 = (const float*)d_in[6];
    const float* W_g1    = (const float*)d_in[7];
    const float* b_g1    = (const float*)d_in[8];
    const float* dirs_g1 = (const float*)d_in[9];
    const float* W_g2    = (const float*)d_in[10];
    const float* b_g2    = (const float*)d_in[11];
    const float* dirs_g2 = (const float*)d_in[12];
    const float* g_l     = (const float*)d_in[13];
    const float* be_l    = (const float*)d_in[14];
    const float* g_m0    = (const float*)d_in[15];
    const float* be_m0   = (const float*)d_in[16];
    const float* g_m1    = (const float*)d_in[17];
    const float* be_m1   = (const float*)d_in[18];
    const float* g_g0    = (const float*)d_in[19];
    const float* be_g0   = (const float*)d_in[20];
    const float* g_g1    = (const float*)d_in[21];
    const float* be_g1   = (const float*)d_in[22];
    const float* g_g2    = (const float*)d_in[23];
    const float* be_g2   = (const float*)d_in[24];
    const float* W_down  = (const float*)d_in[25];
    const float* b_down  = (const float*)d_in[26];
    float* out = (float*)d_out;

    prep_kernel<<<1, 256>>>(dirs_l, dirs_m0, dirs_m1, dirs_g0, dirs_g1, dirs_g2);
    knn_kernel<<<ROWS, 256>>>(verts);
    surf_kernel<<<ROWS, DD>>>();

    stats3_kernel<<<dim3(PART, 3), DD>>>();
    finalize_kernel<<<3, DD>>>(0, g_l, be_l, 1, g_m0, be_m0, 3, g_g0, be_g0);

    // medium scale layer 1
    gemm_kernel<<<ROWS/16, 256>>>(1, 1, W_m1, b_m1);
    convlayer_kernel<20><<<ROWS, DD>>>(2, 1);
    stats_kernel<<<PART, DD>>>(1, 2);

    // global scale layer 1
    gemm_kernel<<<ROWS/16, 256>>>(2, 3, W_g1, b_g1);
    convlayer_kernel<100><<<ROWS, DD>>>(4, 2);
    stats_kernel<<<PART, DD>>>(2, 4);
    finalize_kernel<<<2, DD>>>(2, g_m1, be_m1, 4, g_g1, be_g1, -1, (const float*)0, (const float*)0);

    // global scale layer 2
    gemm_kernel<<<ROWS/16, 256>>>(2, 4, W_g2, b_g2);
    convlayer_kernel<100><<<ROWS, DD>>>(5, 2);
    stats_kernel<<<PART, DD>>>(2, 5);
    finalize_kernel<<<1, DD>>>(5, g_g2, be_g2, -1, (const float*)0, (const float*)0, -1, (const float*)0, (const float*)0);

    final_kernel<<<ROWS/16, 256>>>(W_down, b_down, out);
}